// round 12
// baseline (speedup 1.0000x reference)
#include <cuda_runtime.h>
#include <cuda_bf16.h>
#include <cstdint>
#include <math.h>

#define NN 100000
#define NE 1600000
#define D  128
#define NG 1000
#define NT 12
#define SCAN_BLK 256
#define NBLK ((NN + SCAN_BLK - 1) / SCAN_BLK)   // 391
#define MTILES ((NN + 127) / 128)               // 782

// ---------------------------------------------------------------------------
// Scratch (__device__ globals; no allocation allowed)
// ---------------------------------------------------------------------------
__device__ float g_A[(size_t)NN * D];   // GEMM output xw
__device__ float g_B[(size_t)NN * D];   // layer-1 result (pre-relu)
__device__ int   g_cnt[NN];
__device__ int   g_start[NN];
__device__ int   g_cur[NN];
__device__ int   g_part[512];
__device__ int   g_csr[NE];
// Pre-swizzled bf16 weight images: [layer][hi/lo][32768 bytes]
__device__ __align__(16) uint8_t g_Wimg[2][2][32768];

// Host-side stream/events for fork-join inside the captured graph.
struct ForkResources {
    cudaStream_t s2;
    cudaEvent_t evFork, evJoin;
    ForkResources() {
        cudaStreamCreateWithFlags(&s2, cudaStreamNonBlocking);
        cudaEventCreateWithFlags(&evFork, cudaEventDisableTiming);
        cudaEventCreateWithFlags(&evJoin, cudaEventDisableTiming);
    }
};
static ForkResources g_fork;

// ---------------------------------------------------------------------------
// PTX helpers (legacy tensor core path: compiles under plain sm_103)
// ---------------------------------------------------------------------------
__device__ __forceinline__ uint32_t smem_to_u32(const void* smem_ptr) {
    uint32_t addr;
    asm("{ .reg .u64 tmp; cvta.to.shared.u64 tmp, %1; cvt.u32.u64 %0, tmp; }"
        : "=r"(addr) : "l"(smem_ptr));
    return addr;
}
#define LDMX4(r, addr) \
    asm volatile("ldmatrix.sync.aligned.m8n8.x4.shared.b16 {%0,%1,%2,%3}, [%4];" \
        : "=r"((r)[0]), "=r"((r)[1]), "=r"((r)[2]), "=r"((r)[3]) : "r"(addr))
#define MMA16816(d, a, b0, b1) \
    asm volatile("mma.sync.aligned.m16n8k16.row.col.f32.bf16.bf16.f32 " \
        "{%0,%1,%2,%3}, {%4,%5,%6,%7}, {%8,%9}, {%0,%1,%2,%3};" \
        : "+f"((d)[0]), "+f"((d)[1]), "+f"((d)[2]), "+f"((d)[3]) \
        : "r"((a)[0]), "r"((a)[1]), "r"((a)[2]), "r"((a)[3]), "r"(b0), "r"(b1))

__device__ __forceinline__ uint32_t pack_bf16(float lo_elem, float hi_elem) {
    __nv_bfloat162 p = __floats2bfloat162_rn(lo_elem, hi_elem);  // .x -> low 16 bits
    return *reinterpret_cast<uint32_t*>(&p);
}

// ---------------------------------------------------------------------------
// Prep: split W[128,128] (row-major [k][n]) into hi/lo bf16 transposed images
// Wt[n][k], pre-swizzled: byte(n,k) = n*256 + ((kc ^ (n&7))*16) + (k&7)*2
// ---------------------------------------------------------------------------
__global__ void prep_w_kernel(const float* __restrict__ W0,
                              const float* __restrict__ W1) {
    int idx = blockIdx.x * blockDim.x + threadIdx.x;   // 0 .. 16383
    if (idx >= 2 * 128 * 64) return;
    int layer = idx >> 13;
    int r = idx & 8191;
    int n = r >> 6;
    int kp = r & 63;
    int k = kp * 2;
    const float* W = layer ? W1 : W0;
    float w0 = W[(size_t)k * 128 + n];
    float w1 = W[(size_t)(k + 1) * 128 + n];
    __nv_bfloat16 h0 = __float2bfloat16_rn(w0);
    __nv_bfloat16 h1 = __float2bfloat16_rn(w1);
    uint32_t hp = pack_bf16(__bfloat162float(h0), __bfloat162float(h1));
    uint32_t lp = pack_bf16(w0 - __bfloat162float(h0), w1 - __bfloat162float(h1));
    int kc = k >> 3;
    uint32_t byte = (uint32_t)n * 256 + (uint32_t)((kc ^ (n & 7)) * 16) + (uint32_t)((k & 7) * 2);
    *reinterpret_cast<uint32_t*>(&g_Wimg[layer][0][byte]) = hp;
    *reinterpret_cast<uint32_t*>(&g_Wimg[layer][1][byte]) = lp;
}

// ---------------------------------------------------------------------------
// CSR build
// ---------------------------------------------------------------------------
__global__ void zero_cnt_kernel(int* __restrict__ cnt) {
    int i = blockIdx.x * blockDim.x + threadIdx.x;
    if (i < NN) cnt[i] = 0;
}
__global__ void zero_out_kernel(float* __restrict__ out) {
    int i = blockIdx.x * blockDim.x + threadIdx.x;
    if (i < NG * NT) out[i] = 0.f;
}
__global__ void hist_kernel(const int* __restrict__ ei, int* __restrict__ cnt) {
    int e = blockIdx.x * blockDim.x + threadIdx.x;
    if (e < NE) atomicAdd(&cnt[ei[NE + e]], 1);
}
__global__ void partial_sums_kernel(const int* __restrict__ cnt, int* __restrict__ part) {
    __shared__ int wsum[8];
    int i = blockIdx.x * SCAN_BLK + threadIdx.x;
    int v = (i < NN) ? cnt[i] : 0;
#pragma unroll
    for (int o = 16; o > 0; o >>= 1) v += __shfl_down_sync(0xffffffffu, v, o);
    int lane = threadIdx.x & 31, wid = threadIdx.x >> 5;
    if (lane == 0) wsum[wid] = v;
    __syncthreads();
    if (threadIdx.x == 0) {
        int s = 0;
#pragma unroll
        for (int w = 0; w < 8; w++) s += wsum[w];
        part[blockIdx.x] = s;
    }
}
__global__ void scan_partials_kernel(int* __restrict__ part) {
    __shared__ int s[512];
    int t = threadIdx.x;
    s[t] = (t < NBLK) ? part[t] : 0;
    __syncthreads();
    for (int o = 1; o < 512; o <<= 1) {
        int v = (t >= o) ? s[t - o] : 0;
        __syncthreads();
        s[t] += v;
        __syncthreads();
    }
    if (t < NBLK) part[t] = (t == 0) ? 0 : s[t - 1];
}
__global__ void make_offsets_kernel(const int* __restrict__ cnt,
                                    const int* __restrict__ part,
                                    int* __restrict__ start,
                                    int* __restrict__ cur) {
    __shared__ int wsum[8];
    int i = blockIdx.x * SCAN_BLK + threadIdx.x;
    int v = (i < NN) ? cnt[i] : 0;
    int lane = threadIdx.x & 31, wid = threadIdx.x >> 5;
    int x = v;
#pragma unroll
    for (int o = 1; o < 32; o <<= 1) {
        int y = __shfl_up_sync(0xffffffffu, x, o);
        if (lane >= o) x += y;
    }
    if (lane == 31) wsum[wid] = x;
    __syncthreads();
    if (wid == 0) {
        int w = (lane < 8) ? wsum[lane] : 0;
#pragma unroll
        for (int o = 1; o < 8; o <<= 1) {
            int y = __shfl_up_sync(0xffffffffu, w, o);
            if (lane >= o) w += y;
        }
        if (lane < 8) wsum[lane] = w;
    }
    __syncthreads();
    int ex = x - v + ((wid > 0) ? wsum[wid - 1] : 0) + part[blockIdx.x];
    if (i < NN) { start[i] = ex; cur[i] = ex; }
}
__global__ void fill_csr_kernel(const int* __restrict__ ei,
                                int* __restrict__ cur, int* __restrict__ csr) {
    int e = blockIdx.x * blockDim.x + threadIdx.x;
    if (e >= NE) return;
    int s = ei[e];
    int d = ei[NE + e];
    int p = atomicAdd(&cur[d], 1);
    csr[p] = s;
}

// ---------------------------------------------------------------------------
// Tensor-core GEMM via legacy mma.sync (bf16x3 split), 128-row tiles,
// double-buffered A staging (R10-proven configuration).
// SMEM: Wt_hi 32KB | Wt_lo 32KB | A dbuf 2 x (hi 4KB + lo 4KB) = 80 KB
// ---------------------------------------------------------------------------
#define SW_HI 0
#define SW_LO 32768
#define SA    65536
#define SM_TOTAL 81920

__global__ __launch_bounds__(256, 2) void gemm_mma_kernel(
    const float* __restrict__ in, const uint8_t* __restrict__ wimg_hi,
    const uint8_t* __restrict__ wimg_lo, float* __restrict__ out, int relu_in)
{
    extern __shared__ char smem[];
    const uint32_t sb = smem_to_u32(smem);
    const int tid = threadIdx.x;
    const int warp = tid >> 5;
    const int lane = tid & 31;
    const int row0 = blockIdx.x * 128;

    {
        const uint4* sh = (const uint4*)wimg_hi;
        const uint4* sl = (const uint4*)wimg_lo;
        uint4* dh = (uint4*)(smem + SW_HI);
        uint4* dl = (uint4*)(smem + SW_LO);
        for (int i = tid; i < 2048; i += 256) { dh[i] = sh[i]; dl[i] = sl[i]; }
    }

    float d[16][4];
#pragma unroll
    for (int t = 0; t < 16; t++)
#pragma unroll
        for (int j = 0; j < 4; j++) d[t][j] = 0.f;

    const int arow = tid >> 1;
    const int ahalf = tid & 1;
    const int gr_a = row0 + arow;
    const uint32_t a_st_byte = (uint32_t)arow * 32 + (uint32_t)((ahalf ^ ((arow >> 2) & 1)) << 4);

    const int lrow = (warp << 4) + (lane & 15);
    const int lh = lane >> 4;
    const uint32_t a_ld_off = (uint32_t)lrow * 32 + (uint32_t)((lh ^ ((lrow >> 2) & 1)) << 4);

    const int nLoc = ((lane >> 4) << 3) + (lane & 7);
    const int kcSel = (lane >> 3) & 1;

    auto stage = [&](int ks, int buf) {
        const int k0 = ks * 16;
        const uint32_t abase = (uint32_t)(SA + buf * 8192);
        float4 va = make_float4(0.f, 0.f, 0.f, 0.f), vb = va;
        if (gr_a < NN) {
            const float* src = in + (size_t)gr_a * D + k0 + ahalf * 8;
            va = *(const float4*)(src);
            vb = *(const float4*)(src + 4);
            if (relu_in) {
                va.x = fmaxf(va.x, 0.f); va.y = fmaxf(va.y, 0.f);
                va.z = fmaxf(va.z, 0.f); va.w = fmaxf(va.w, 0.f);
                vb.x = fmaxf(vb.x, 0.f); vb.y = fmaxf(vb.y, 0.f);
                vb.z = fmaxf(vb.z, 0.f); vb.w = fmaxf(vb.w, 0.f);
            }
        }
        float f[8] = {va.x, va.y, va.z, va.w, vb.x, vb.y, vb.z, vb.w};
        uint32_t hi[4], lo[4];
#pragma unroll
        for (int j = 0; j < 4; j++) {
            float x = f[2 * j], y = f[2 * j + 1];
            __nv_bfloat16 hx = __float2bfloat16_rn(x);
            __nv_bfloat16 hy = __float2bfloat16_rn(y);
            hi[j] = pack_bf16(__bfloat162float(hx), __bfloat162float(hy));
            lo[j] = pack_bf16(x - __bfloat162float(hx), y - __bfloat162float(hy));
        }
        *(uint4*)(smem + abase + a_st_byte) = make_uint4(hi[0], hi[1], hi[2], hi[3]);
        *(uint4*)(smem + abase + 4096 + a_st_byte) = make_uint4(lo[0], lo[1], lo[2], lo[3]);
    };

    stage(0, 0);
    __syncthreads();

    for (int ks = 0; ks < 8; ks++) {
        const int buf = ks & 1;
        const uint32_t abase = sb + SA + (uint32_t)buf * 8192;

        uint32_t ah[4], al[4];
        LDMX4(ah, abase + a_ld_off);
        LDMX4(al, abase + 4096 + a_ld_off);

        if (ks < 7) stage(ks + 1, buf ^ 1);

#pragma unroll
        for (int j = 0; j < 8; j++) {
            const int n = (j << 4) + nLoc;
            const int kc = (ks << 1) + kcSel;
            const uint32_t boff = (uint32_t)n * 256 + (uint32_t)((kc ^ (n & 7)) << 4);
            uint32_t bh[4], bl[4];
            LDMX4(bh, sb + SW_HI + boff);
            LDMX4(bl, sb + SW_LO + boff);
            MMA16816(d[2 * j],     ah, bh[0], bh[1]);
            MMA16816(d[2 * j],     ah, bl[0], bl[1]);
            MMA16816(d[2 * j],     al, bh[0], bh[1]);
            MMA16816(d[2 * j + 1], ah, bh[2], bh[3]);
            MMA16816(d[2 * j + 1], ah, bl[2], bl[3]);
            MMA16816(d[2 * j + 1], al, bh[2], bh[3]);
        }
        __syncthreads();
    }

    const int r0g = row0 + (warp << 4) + (lane >> 2);
    const int cbase = (lane & 3) * 2;
#pragma unroll
    for (int t = 0; t < 16; t++) {
        const int col = t * 8 + cbase;
        if (r0g < NN)
            *(float2*)(out + (size_t)r0g * D + col) = make_float2(d[t][0], d[t][1]);
        if (r0g + 8 < NN)
            *(float2*)(out + (size_t)(r0g + 8) * D + col) = make_float2(d[t][2], d[t][3]);
    }
}

// ---------------------------------------------------------------------------
// Gather: row = bias + A[i] + sum_{j in nbrs(i)} A[j].   1 warp / node.
// mode 0: write fp32 row to outf (layer-1).
// mode 1: fused head — relu(row) @ Wf + bf -> sigmoid -> atomicAdd(out[g], /sz).
// ---------------------------------------------------------------------------
__global__ __launch_bounds__(256) void gather_kernel(
    const float* __restrict__ A, const int* __restrict__ start,
    const int* __restrict__ cnt, const int* __restrict__ csr,
    const float* __restrict__ bias, float* __restrict__ outf,
    const float* __restrict__ Wf, const float* __restrict__ bf,
    const int* __restrict__ gsz, float* __restrict__ gout, int mode)
{
    const int n = (blockIdx.x * blockDim.x + threadIdx.x) >> 5;
    if (n >= NN) return;
    const int lane = threadIdx.x & 31;
    const int c = lane * 4;

    float4 acc = *(const float4*)(A + (size_t)n * D + c);
    float4 b = *(const float4*)(bias + c);
    acc.x += b.x; acc.y += b.y; acc.z += b.z; acc.w += b.w;

    const int s0 = start[n];
    const int deg = cnt[n];

    for (int k0 = 0; k0 < deg; k0 += 32) {
        int idx = (k0 + lane < deg) ? csr[s0 + k0 + lane] : 0;
        int m = min(32, deg - k0);
        int j = 0;
        for (; j + 4 <= m; j += 4) {
            int n0 = __shfl_sync(0xffffffffu, idx, j);
            int n1 = __shfl_sync(0xffffffffu, idx, j + 1);
            int n2 = __shfl_sync(0xffffffffu, idx, j + 2);
            int n3 = __shfl_sync(0xffffffffu, idx, j + 3);
            float4 v0 = *(const float4*)(A + (size_t)n0 * D + c);
            float4 v1 = *(const float4*)(A + (size_t)n1 * D + c);
            float4 v2 = *(const float4*)(A + (size_t)n2 * D + c);
            float4 v3 = *(const float4*)(A + (size_t)n3 * D + c);
            acc.x += v0.x + v1.x + v2.x + v3.x;
            acc.y += v0.y + v1.y + v2.y + v3.y;
            acc.z += v0.z + v1.z + v2.z + v3.z;
            acc.w += v0.w + v1.w + v2.w + v3.w;
        }
        for (; j < m; j++) {
            int nb = __shfl_sync(0xffffffffu, idx, j);
            float4 v = *(const float4*)(A + (size_t)nb * D + c);
            acc.x += v.x; acc.y += v.y; acc.z += v.z; acc.w += v.w;
        }
    }

    if (mode == 0) {
        *(float4*)(outf + (size_t)n * D + c) = acc;
        return;
    }

    // ---- fused head: relu -> @Wf + bf -> sigmoid -> segment-mean atomic ----
    acc.x = fmaxf(acc.x, 0.f); acc.y = fmaxf(acc.y, 0.f);
    acc.z = fmaxf(acc.z, 0.f); acc.w = fmaxf(acc.w, 0.f);

    float a[NT];
#pragma unroll
    for (int t = 0; t < NT; t++) a[t] = 0.f;
    const float* w0 = Wf + (size_t)c * NT;
#pragma unroll
    for (int t = 0; t < NT; t++) {
        a[t] = fmaf(acc.x, __ldg(w0 + t),
               fmaf(acc.y, __ldg(w0 + NT + t),
               fmaf(acc.z, __ldg(w0 + 2 * NT + t),
               fmaf(acc.w, __ldg(w0 + 3 * NT + t), a[t]))));
    }
    // butterfly reduce each logit across the warp
#pragma unroll
    for (int t = 0; t < NT; t++) {
#pragma unroll
        for (int o = 16; o > 0; o >>= 1)
            a[t] += __shfl_xor_sync(0xffffffffu, a[t], o);
    }
    if (lane < NT) {
        const int g = n / 100;
        const float inv_sz = 1.f / (float)gsz[g];
        float s = 1.f / (1.f + expf(-(a[lane] + bf[lane])));
        atomicAdd(&gout[(size_t)g * NT + lane], s * inv_sz);
    }
}

// ---------------------------------------------------------------------------
extern "C" void kernel_launch(void* const* d_in, const int* in_sizes, int n_in,
                              void* d_out, int out_size)
{
    const float* X   = (const float*)d_in[0];
    const int*   ei  = (const int*)d_in[1];
    const int*   gsz = (const int*)d_in[2];
    const float* W0  = (const float*)d_in[3];
    const float* b0  = (const float*)d_in[4];
    const float* W1  = (const float*)d_in[5];
    const float* b1  = (const float*)d_in[6];
    const float* Wf  = (const float*)d_in[7];
    const float* bf  = (const float*)d_in[8];
    float* out = (float*)d_out;

    float *A, *B;
    int *cnt, *start, *cur, *part, *csr;
    uint8_t* wimg;
    cudaGetSymbolAddress((void**)&A, g_A);
    cudaGetSymbolAddress((void**)&B, g_B);
    cudaGetSymbolAddress((void**)&cnt, g_cnt);
    cudaGetSymbolAddress((void**)&start, g_start);
    cudaGetSymbolAddress((void**)&cur, g_cur);
    cudaGetSymbolAddress((void**)&part, g_part);
    cudaGetSymbolAddress((void**)&csr, g_csr);
    cudaGetSymbolAddress((void**)&wimg, g_Wimg);

    cudaFuncSetAttribute(gemm_mma_kernel,
                         cudaFuncAttributeMaxDynamicSharedMemorySize, SM_TOTAL);

    const int edge_blocks = (NE + 255) / 256;
    const int node_warp_blocks = (NN * 32 + 255) / 256;

    cudaStream_t s2 = g_fork.s2;

    // ---- fork: CSR build chain + output zeroing on side stream ----
    cudaEventRecord(g_fork.evFork, 0);
    cudaStreamWaitEvent(s2, g_fork.evFork, 0);

    zero_cnt_kernel<<<NBLK, SCAN_BLK, 0, s2>>>(cnt);
    zero_out_kernel<<<(NG * NT + 255) / 256, 256, 0, s2>>>(out);
    hist_kernel<<<edge_blocks, 256, 0, s2>>>(ei, cnt);
    partial_sums_kernel<<<NBLK, SCAN_BLK, 0, s2>>>(cnt, part);
    scan_partials_kernel<<<1, 512, 0, s2>>>(part);
    make_offsets_kernel<<<NBLK, SCAN_BLK, 0, s2>>>(cnt, part, start, cur);
    fill_csr_kernel<<<edge_blocks, 256, 0, s2>>>(ei, cur, csr);
    cudaEventRecord(g_fork.evJoin, s2);

    // ---- main stream: weight prep + GEMM1 (concurrent with CSR) ----
    const uint8_t* w0h = wimg;
    const uint8_t* w0l = wimg + 32768;
    const uint8_t* w1h = wimg + 65536;
    const uint8_t* w1l = wimg + 98304;

    prep_w_kernel<<<64, 256>>>(W0, W1);
    gemm_mma_kernel<<<MTILES, 256, SM_TOTAL>>>(X, w0h, w0l, A, 0);

    // ---- join: gather needs both GEMM1 (A) and the CSR arrays ----
    cudaStreamWaitEvent(0, g_fork.evJoin, 0);

    // Layer 1 aggregate: B = b0 + A + gather(A)
    gather_kernel<<<node_warp_blocks, 256>>>(A, start, cnt, csr, b0, B,
                                             nullptr, nullptr, nullptr, nullptr, 0);

    // Layer 2: A = relu(B)@W1 ; fused aggregate+head -> out
    gemm_mma_kernel<<<MTILES, 256, SM_TOTAL>>>(B, w1h, w1l, A, 1);
    gather_kernel<<<node_warp_blocks, 256>>>(A, start, cnt, csr, b1, nullptr,
                                             Wf, bf, gsz, out, 1);
}

// round 14
// speedup vs baseline: 1.5662x; 1.5662x over previous
#include <cuda_runtime.h>
#include <cuda_bf16.h>
#include <cstdint>
#include <math.h>

#define NN 100000
#define NE 1600000
#define D  128
#define NG 1000
#define NT 12
#define SCAN_BLK 256
#define NBLK ((NN + SCAN_BLK - 1) / SCAN_BLK)   // 391
#define MTILES ((NN + 127) / 128)               // 782
#define HALF_TILES 391
#define HALF_ROWS  (HALF_TILES * 128)           // 50048

// ---------------------------------------------------------------------------
// Scratch (__device__ globals; no allocation allowed)
// ---------------------------------------------------------------------------
__device__ float g_A[(size_t)NN * D];   // GEMM1 output xw
__device__ float g_A2[(size_t)NN * D];  // GEMM2 output (separate: avoids WAR race)
__device__ float g_B[(size_t)NN * D];   // layer-1 result (pre-relu)
__device__ float g_C[(size_t)NN * D];   // layer-2 result (pre-relu)
__device__ int   g_cnt[NN];
__device__ int   g_start[NN];
__device__ int   g_cur[NN];
__device__ int   g_part[512];
__device__ int   g_csr[NE];
// Pre-swizzled bf16 weight images: [layer][hi/lo][32768 bytes]
__device__ __align__(16) uint8_t g_Wimg[2][2][32768];

// Host-side stream/events for fork-join inside the captured graph.
struct ForkResources {
    cudaStream_t s2;
    cudaEvent_t evFork, evJoin, evH1, evH2;
    ForkResources() {
        cudaStreamCreateWithFlags(&s2, cudaStreamNonBlocking);
        cudaEventCreateWithFlags(&evFork, cudaEventDisableTiming);
        cudaEventCreateWithFlags(&evJoin, cudaEventDisableTiming);
        cudaEventCreateWithFlags(&evH1, cudaEventDisableTiming);
        cudaEventCreateWithFlags(&evH2, cudaEventDisableTiming);
    }
};
static ForkResources g_fork;

// ---------------------------------------------------------------------------
// PTX helpers (legacy tensor core path: compiles under plain sm_103)
// ---------------------------------------------------------------------------
__device__ __forceinline__ uint32_t smem_to_u32(const void* smem_ptr) {
    uint32_t addr;
    asm("{ .reg .u64 tmp; cvta.to.shared.u64 tmp, %1; cvt.u32.u64 %0, tmp; }"
        : "=r"(addr) : "l"(smem_ptr));
    return addr;
}
#define LDMX4(r, addr) \
    asm volatile("ldmatrix.sync.aligned.m8n8.x4.shared.b16 {%0,%1,%2,%3}, [%4];" \
        : "=r"((r)[0]), "=r"((r)[1]), "=r"((r)[2]), "=r"((r)[3]) : "r"(addr))
#define MMA16816(d, a, b0, b1) \
    asm volatile("mma.sync.aligned.m16n8k16.row.col.f32.bf16.bf16.f32 " \
        "{%0,%1,%2,%3}, {%4,%5,%6,%7}, {%8,%9}, {%0,%1,%2,%3};" \
        : "+f"((d)[0]), "+f"((d)[1]), "+f"((d)[2]), "+f"((d)[3]) \
        : "r"((a)[0]), "r"((a)[1]), "r"((a)[2]), "r"((a)[3]), "r"(b0), "r"(b1))

__device__ __forceinline__ uint32_t pack_bf16(float lo_elem, float hi_elem) {
    __nv_bfloat162 p = __floats2bfloat162_rn(lo_elem, hi_elem);  // .x -> low 16 bits
    return *reinterpret_cast<uint32_t*>(&p);
}

// ---------------------------------------------------------------------------
// Prep: split W[128,128] (row-major [k][n]) into hi/lo bf16 transposed images
// ---------------------------------------------------------------------------
__global__ void prep_w_kernel(const float* __restrict__ W0,
                              const float* __restrict__ W1) {
    int idx = blockIdx.x * blockDim.x + threadIdx.x;   // 0 .. 16383
    if (idx >= 2 * 128 * 64) return;
    int layer = idx >> 13;
    int r = idx & 8191;
    int n = r >> 6;
    int kp = r & 63;
    int k = kp * 2;
    const float* W = layer ? W1 : W0;
    float w0 = W[(size_t)k * 128 + n];
    float w1 = W[(size_t)(k + 1) * 128 + n];
    __nv_bfloat16 h0 = __float2bfloat16_rn(w0);
    __nv_bfloat16 h1 = __float2bfloat16_rn(w1);
    uint32_t hp = pack_bf16(__bfloat162float(h0), __bfloat162float(h1));
    uint32_t lp = pack_bf16(w0 - __bfloat162float(h0), w1 - __bfloat162float(h1));
    int kc = k >> 3;
    uint32_t byte = (uint32_t)n * 256 + (uint32_t)((kc ^ (n & 7)) * 16) + (uint32_t)((k & 7) * 2);
    *reinterpret_cast<uint32_t*>(&g_Wimg[layer][0][byte]) = hp;
    *reinterpret_cast<uint32_t*>(&g_Wimg[layer][1][byte]) = lp;
}

// ---------------------------------------------------------------------------
// CSR build
// ---------------------------------------------------------------------------
__global__ void zero_cnt_kernel(int* __restrict__ cnt) {
    int i = blockIdx.x * blockDim.x + threadIdx.x;
    if (i < NN) cnt[i] = 0;
}
__global__ void hist_kernel(const int* __restrict__ ei, int* __restrict__ cnt) {
    int e = blockIdx.x * blockDim.x + threadIdx.x;
    if (e < NE) atomicAdd(&cnt[ei[NE + e]], 1);
}
__global__ void partial_sums_kernel(const int* __restrict__ cnt, int* __restrict__ part) {
    __shared__ int wsum[8];
    int i = blockIdx.x * SCAN_BLK + threadIdx.x;
    int v = (i < NN) ? cnt[i] : 0;
#pragma unroll
    for (int o = 16; o > 0; o >>= 1) v += __shfl_down_sync(0xffffffffu, v, o);
    int lane = threadIdx.x & 31, wid = threadIdx.x >> 5;
    if (lane == 0) wsum[wid] = v;
    __syncthreads();
    if (threadIdx.x == 0) {
        int s = 0;
#pragma unroll
        for (int w = 0; w < 8; w++) s += wsum[w];
        part[blockIdx.x] = s;
    }
}
__global__ void scan_partials_kernel(int* __restrict__ part) {
    __shared__ int s[512];
    int t = threadIdx.x;
    s[t] = (t < NBLK) ? part[t] : 0;
    __syncthreads();
    for (int o = 1; o < 512; o <<= 1) {
        int v = (t >= o) ? s[t - o] : 0;
        __syncthreads();
        s[t] += v;
        __syncthreads();
    }
    if (t < NBLK) part[t] = (t == 0) ? 0 : s[t - 1];
}
__global__ void make_offsets_kernel(const int* __restrict__ cnt,
                                    const int* __restrict__ part,
                                    int* __restrict__ start,
                                    int* __restrict__ cur) {
    __shared__ int wsum[8];
    int i = blockIdx.x * SCAN_BLK + threadIdx.x;
    int v = (i < NN) ? cnt[i] : 0;
    int lane = threadIdx.x & 31, wid = threadIdx.x >> 5;
    int x = v;
#pragma unroll
    for (int o = 1; o < 32; o <<= 1) {
        int y = __shfl_up_sync(0xffffffffu, x, o);
        if (lane >= o) x += y;
    }
    if (lane == 31) wsum[wid] = x;
    __syncthreads();
    if (wid == 0) {
        int w = (lane < 8) ? wsum[lane] : 0;
#pragma unroll
        for (int o = 1; o < 8; o <<= 1) {
            int y = __shfl_up_sync(0xffffffffu, w, o);
            if (lane >= o) w += y;
        }
        if (lane < 8) wsum[lane] = w;
    }
    __syncthreads();
    int ex = x - v + ((wid > 0) ? wsum[wid - 1] : 0) + part[blockIdx.x];
    if (i < NN) { start[i] = ex; cur[i] = ex; }
}
__global__ void fill_csr_kernel(const int* __restrict__ ei,
                                int* __restrict__ cur, int* __restrict__ csr) {
    int e = blockIdx.x * blockDim.x + threadIdx.x;
    if (e >= NE) return;
    int s = ei[e];
    int d = ei[NE + e];
    int p = atomicAdd(&cur[d], 1);
    csr[p] = s;
}

// ---------------------------------------------------------------------------
// Tensor-core GEMM via legacy mma.sync (bf16x3 split), 128-row tiles,
// double-buffered A staging. row_base selects the tile range (pipelining).
// SMEM: Wt_hi 32KB | Wt_lo 32KB | A dbuf 2 x (hi 4KB + lo 4KB) = 80 KB
// ---------------------------------------------------------------------------
#define SW_HI 0
#define SW_LO 32768
#define SA    65536
#define SM_TOTAL 81920

__global__ __launch_bounds__(256, 2) void gemm_mma_kernel(
    const float* __restrict__ in, const uint8_t* __restrict__ wimg_hi,
    const uint8_t* __restrict__ wimg_lo, float* __restrict__ out,
    int relu_in, int row_base)
{
    extern __shared__ char smem[];
    const uint32_t sb = smem_to_u32(smem);
    const int tid = threadIdx.x;
    const int warp = tid >> 5;
    const int lane = tid & 31;
    const int row0 = row_base + blockIdx.x * 128;

    {
        const uint4* sh = (const uint4*)wimg_hi;
        const uint4* sl = (const uint4*)wimg_lo;
        uint4* dh = (uint4*)(smem + SW_HI);
        uint4* dl = (uint4*)(smem + SW_LO);
        for (int i = tid; i < 2048; i += 256) { dh[i] = sh[i]; dl[i] = sl[i]; }
    }

    float d[16][4];
#pragma unroll
    for (int t = 0; t < 16; t++)
#pragma unroll
        for (int j = 0; j < 4; j++) d[t][j] = 0.f;

    const int arow = tid >> 1;
    const int ahalf = tid & 1;
    const int gr_a = row0 + arow;
    const uint32_t a_st_byte = (uint32_t)arow * 32 + (uint32_t)((ahalf ^ ((arow >> 2) & 1)) << 4);

    const int lrow = (warp << 4) + (lane & 15);
    const int lh = lane >> 4;
    const uint32_t a_ld_off = (uint32_t)lrow * 32 + (uint32_t)((lh ^ ((lrow >> 2) & 1)) << 4);

    const int nLoc = ((lane >> 4) << 3) + (lane & 7);
    const int kcSel = (lane >> 3) & 1;

    auto stage = [&](int ks, int buf) {
        const int k0 = ks * 16;
        const uint32_t abase = (uint32_t)(SA + buf * 8192);
        float4 va = make_float4(0.f, 0.f, 0.f, 0.f), vb = va;
        if (gr_a < NN) {
            const float* src = in + (size_t)gr_a * D + k0 + ahalf * 8;
            va = *(const float4*)(src);
            vb = *(const float4*)(src + 4);
            if (relu_in) {
                va.x = fmaxf(va.x, 0.f); va.y = fmaxf(va.y, 0.f);
                va.z = fmaxf(va.z, 0.f); va.w = fmaxf(va.w, 0.f);
                vb.x = fmaxf(vb.x, 0.f); vb.y = fmaxf(vb.y, 0.f);
                vb.z = fmaxf(vb.z, 0.f); vb.w = fmaxf(vb.w, 0.f);
            }
        }
        float f[8] = {va.x, va.y, va.z, va.w, vb.x, vb.y, vb.z, vb.w};
        uint32_t hi[4], lo[4];
#pragma unroll
        for (int j = 0; j < 4; j++) {
            float x = f[2 * j], y = f[2 * j + 1];
            __nv_bfloat16 hx = __float2bfloat16_rn(x);
            __nv_bfloat16 hy = __float2bfloat16_rn(y);
            hi[j] = pack_bf16(__bfloat162float(hx), __bfloat162float(hy));
            lo[j] = pack_bf16(x - __bfloat162float(hx), y - __bfloat162float(hy));
        }
        *(uint4*)(smem + abase + a_st_byte) = make_uint4(hi[0], hi[1], hi[2], hi[3]);
        *(uint4*)(smem + abase + 4096 + a_st_byte) = make_uint4(lo[0], lo[1], lo[2], lo[3]);
    };

    stage(0, 0);
    __syncthreads();

    for (int ks = 0; ks < 8; ks++) {
        const int buf = ks & 1;
        const uint32_t abase = sb + SA + (uint32_t)buf * 8192;

        uint32_t ah[4], al[4];
        LDMX4(ah, abase + a_ld_off);
        LDMX4(al, abase + 4096 + a_ld_off);

        if (ks < 7) stage(ks + 1, buf ^ 1);

#pragma unroll
        for (int j = 0; j < 8; j++) {
            const int n = (j << 4) + nLoc;
            const int kc = (ks << 1) + kcSel;
            const uint32_t boff = (uint32_t)n * 256 + (uint32_t)((kc ^ (n & 7)) << 4);
            uint32_t bh[4], bl[4];
            LDMX4(bh, sb + SW_HI + boff);
            LDMX4(bl, sb + SW_LO + boff);
            MMA16816(d[2 * j],     ah, bh[0], bh[1]);
            MMA16816(d[2 * j],     ah, bl[0], bl[1]);
            MMA16816(d[2 * j],     al, bh[0], bh[1]);
            MMA16816(d[2 * j + 1], ah, bh[2], bh[3]);
            MMA16816(d[2 * j + 1], ah, bl[2], bl[3]);
            MMA16816(d[2 * j + 1], al, bh[2], bh[3]);
        }
        __syncthreads();
    }

    const int r0g = row0 + (warp << 4) + (lane >> 2);
    const int cbase = (lane & 3) * 2;
#pragma unroll
    for (int t = 0; t < 16; t++) {
        const int col = t * 8 + cbase;
        if (r0g < NN)
            *(float2*)(out + (size_t)r0g * D + col) = make_float2(d[t][0], d[t][1]);
        if (r0g + 8 < NN)
            *(float2*)(out + (size_t)(r0g + 8) * D + col) = make_float2(d[t][2], d[t][3]);
    }
}

// ---------------------------------------------------------------------------
// Gather over node range [node_base, node_end): out[i] = bias + A[i] + sum nbrs
// ---------------------------------------------------------------------------
__global__ __launch_bounds__(256) void gather_kernel(
    const float* __restrict__ A, const int* __restrict__ start,
    const int* __restrict__ cnt, const int* __restrict__ csr,
    const float* __restrict__ bias, float* __restrict__ out,
    int node_base, int node_end)
{
    const int n = node_base + ((blockIdx.x * blockDim.x + threadIdx.x) >> 5);
    if (n >= node_end) return;
    const int lane = threadIdx.x & 31;
    const int c = lane * 4;

    float4 acc = *(const float4*)(A + (size_t)n * D + c);
    float4 b = *(const float4*)(bias + c);
    acc.x += b.x; acc.y += b.y; acc.z += b.z; acc.w += b.w;

    const int s0 = start[n];
    const int deg = cnt[n];

    for (int k0 = 0; k0 < deg; k0 += 32) {
        int idx = (k0 + lane < deg) ? csr[s0 + k0 + lane] : 0;
        int m = min(32, deg - k0);
        int j = 0;
        for (; j + 4 <= m; j += 4) {
            int n0 = __shfl_sync(0xffffffffu, idx, j);
            int n1 = __shfl_sync(0xffffffffu, idx, j + 1);
            int n2 = __shfl_sync(0xffffffffu, idx, j + 2);
            int n3 = __shfl_sync(0xffffffffu, idx, j + 3);
            float4 v0 = *(const float4*)(A + (size_t)n0 * D + c);
            float4 v1 = *(const float4*)(A + (size_t)n1 * D + c);
            float4 v2 = *(const float4*)(A + (size_t)n2 * D + c);
            float4 v3 = *(const float4*)(A + (size_t)n3 * D + c);
            acc.x += v0.x + v1.x + v2.x + v3.x;
            acc.y += v0.y + v1.y + v2.y + v3.y;
            acc.z += v0.z + v1.z + v2.z + v3.z;
            acc.w += v0.w + v1.w + v2.w + v3.w;
        }
        for (; j < m; j++) {
            int nb = __shfl_sync(0xffffffffu, idx, j);
            float4 v = *(const float4*)(A + (size_t)nb * D + c);
            acc.x += v.x; acc.y += v.y; acc.z += v.z; acc.w += v.w;
        }
    }
    *(float4*)(out + (size_t)n * D + c) = acc;
}

// ---------------------------------------------------------------------------
// Readout
// ---------------------------------------------------------------------------
__global__ __launch_bounds__(128) void readout_kernel(
    const float* __restrict__ h, const float* __restrict__ Wf,
    const float* __restrict__ bf, const int* __restrict__ gsz,
    float* __restrict__ out)
{
    __shared__ float Wfs[D][NT];
    __shared__ float bfs[NT];
    __shared__ float sums[NT];

    const int tid = threadIdx.x;
    const int g = blockIdx.x;

    for (int i = tid; i < D * NT; i += 128) Wfs[i / NT][i % NT] = Wf[i];
    if (tid < NT) { bfs[tid] = bf[tid]; sums[tid] = 0.f; }
    __syncthreads();

    const int sz = gsz[g];
    if (tid < sz) {
        const float* row = h + ((size_t)g * 100 + tid) * D;
        float a[NT];
#pragma unroll
        for (int t = 0; t < NT; t++) a[t] = bfs[t];
        for (int k0 = 0; k0 < D; k0 += 4) {
            float4 hv = *(const float4*)(row + k0);
            hv.x = fmaxf(hv.x, 0.f); hv.y = fmaxf(hv.y, 0.f);
            hv.z = fmaxf(hv.z, 0.f); hv.w = fmaxf(hv.w, 0.f);
#pragma unroll
            for (int t = 0; t < NT; t++) {
                a[t] = fmaf(hv.x, Wfs[k0 + 0][t], a[t]);
                a[t] = fmaf(hv.y, Wfs[k0 + 1][t], a[t]);
                a[t] = fmaf(hv.z, Wfs[k0 + 2][t], a[t]);
                a[t] = fmaf(hv.w, Wfs[k0 + 3][t], a[t]);
            }
        }
#pragma unroll
        for (int t = 0; t < NT; t++) {
            float s = 1.f / (1.f + expf(-a[t]));
            atomicAdd(&sums[t], s);
        }
    }
    __syncthreads();
    if (tid < NT) out[(size_t)g * NT + tid] = sums[tid] / (float)sz;
}

// ---------------------------------------------------------------------------
extern "C" void kernel_launch(void* const* d_in, const int* in_sizes, int n_in,
                              void* d_out, int out_size)
{
    const float* X   = (const float*)d_in[0];
    const int*   ei  = (const int*)d_in[1];
    const int*   gsz = (const int*)d_in[2];
    const float* W0  = (const float*)d_in[3];
    const float* b0  = (const float*)d_in[4];
    const float* W1  = (const float*)d_in[5];
    const float* b1  = (const float*)d_in[6];
    const float* Wf  = (const float*)d_in[7];
    const float* bf  = (const float*)d_in[8];
    float* out = (float*)d_out;

    float *A, *A2, *B, *C;
    int *cnt, *start, *cur, *part, *csr;
    uint8_t* wimg;
    cudaGetSymbolAddress((void**)&A, g_A);
    cudaGetSymbolAddress((void**)&A2, g_A2);
    cudaGetSymbolAddress((void**)&B, g_B);
    cudaGetSymbolAddress((void**)&C, g_C);
    cudaGetSymbolAddress((void**)&cnt, g_cnt);
    cudaGetSymbolAddress((void**)&start, g_start);
    cudaGetSymbolAddress((void**)&cur, g_cur);
    cudaGetSymbolAddress((void**)&part, g_part);
    cudaGetSymbolAddress((void**)&csr, g_csr);
    cudaGetSymbolAddress((void**)&wimg, g_Wimg);

    cudaFuncSetAttribute(gemm_mma_kernel,
                         cudaFuncAttributeMaxDynamicSharedMemorySize, SM_TOTAL);

    const int edge_blocks = (NE + 255) / 256;
    const int h1_blocks = (HALF_ROWS * 32 + 255) / 256;
    const int h2_blocks = ((NN - HALF_ROWS) * 32 + 255) / 256;
    const int full_blocks = (NN * 32 + 255) / 256;

    cudaStream_t s2 = g_fork.s2;

    // ---- fork: CSR build chain on side stream (overlaps prep+GEMM1) ----
    cudaEventRecord(g_fork.evFork, 0);
    cudaStreamWaitEvent(s2, g_fork.evFork, 0);

    zero_cnt_kernel<<<NBLK, SCAN_BLK, 0, s2>>>(cnt);
    hist_kernel<<<edge_blocks, 256, 0, s2>>>(ei, cnt);
    partial_sums_kernel<<<NBLK, SCAN_BLK, 0, s2>>>(cnt, part);
    scan_partials_kernel<<<1, 512, 0, s2>>>(part);
    make_offsets_kernel<<<NBLK, SCAN_BLK, 0, s2>>>(cnt, part, start, cur);
    fill_csr_kernel<<<edge_blocks, 256, 0, s2>>>(ei, cur, csr);
    cudaEventRecord(g_fork.evJoin, s2);

    // ---- main stream: weight prep + GEMM1 (full, X -> A) ----
    const uint8_t* w0h = wimg;
    const uint8_t* w0l = wimg + 32768;
    const uint8_t* w1h = wimg + 65536;
    const uint8_t* w1l = wimg + 98304;

    prep_w_kernel<<<64, 256>>>(W0, W1);
    gemm_mma_kernel<<<MTILES, 256, SM_TOTAL>>>(X, w0h, w0l, A, 0, 0);

    // ---- join CSR, then pipelined layer boundary ----
    cudaStreamWaitEvent(0, g_fork.evJoin, 0);

    // gather1-H1 (nodes [0, 50048)): reads A, writes B[0,H)
    gather_kernel<<<h1_blocks, 256>>>(A, start, cnt, csr, b0, B, 0, HALF_ROWS);
    cudaEventRecord(g_fork.evH1, 0);

    // gather1-H2 on side stream: reads A, writes B[H,NN)  (concurrent w/ GEMM2-T1)
    cudaStreamWaitEvent(s2, g_fork.evH1, 0);
    gather_kernel<<<h2_blocks, 256, 0, s2>>>(A, start, cnt, csr, b0, B,
                                             HALF_ROWS, NN);
    cudaEventRecord(g_fork.evH2, s2);

    // GEMM2-T1: reads B[0,H) (done), writes A2[0,H) — disjoint from gather1-H2
    gemm_mma_kernel<<<HALF_TILES, 256, SM_TOTAL>>>(B, w1h, w1l, A2, 1, 0);

    // GEMM2-T2 needs B rows [H, NN) from gather1-H2
    cudaStreamWaitEvent(0, g_fork.evH2, 0);
    gemm_mma_kernel<<<MTILES - HALF_TILES, 256, SM_TOTAL>>>(B, w1h, w1l, A2, 1,
                                                            HALF_ROWS);

    // Layer-2 aggregate + head
    gather_kernel<<<full_blocks, 256>>>(A2, start, cnt, csr, b1, C, 0, NN);
    readout_kernel<<<NG, 128>>>(C, Wf, bf, gsz, out);
}

// round 16
// speedup vs baseline: 1.6247x; 1.0374x over previous
#include <cuda_runtime.h>
#include <cuda_bf16.h>
#include <cstdint>
#include <math.h>

#define NN 100000
#define NE 1600000
#define D  128
#define NG 1000
#define NT 12
#define SCAN_BLK 256
#define NBLK ((NN + SCAN_BLK - 1) / SCAN_BLK)   // 391
#define MTILES ((NN + 127) / 128)               // 782

// ---------------------------------------------------------------------------
// Scratch (__device__ globals; no allocation allowed)
// ---------------------------------------------------------------------------
__device__ float g_A[(size_t)NN * D];   // GEMM output xw
__device__ float g_B[(size_t)NN * D];   // layer-1 result (pre-relu)
__device__ float g_C[(size_t)NN * D];   // layer-2 result (pre-relu)
__device__ int   g_cnt[NN];
__device__ int   g_start[NN];
__device__ int   g_cur[NN];
__device__ int   g_part[512];
__device__ int   g_csr[NE];
// Pre-swizzled bf16 weight images: [layer][hi/lo][32768 bytes]
__device__ __align__(16) uint8_t g_Wimg[2][2][32768];

// Host-side stream/events for fork-join inside the captured graph.
// Side stream gets GREATEST priority so its CTAs interleave with GEMM1
// instead of queueing behind it.
struct ForkResources {
    cudaStream_t s2;
    cudaEvent_t evFork, evJoin;
    ForkResources() {
        int lo = 0, hi = 0;
        cudaDeviceGetStreamPriorityRange(&lo, &hi);   // hi = greatest priority
        cudaStreamCreateWithPriority(&s2, cudaStreamNonBlocking, hi);
        cudaEventCreateWithFlags(&evFork, cudaEventDisableTiming);
        cudaEventCreateWithFlags(&evJoin, cudaEventDisableTiming);
    }
};
static ForkResources g_fork;

// ---------------------------------------------------------------------------
// PTX helpers (legacy tensor core path: compiles under plain sm_103)
// ---------------------------------------------------------------------------
__device__ __forceinline__ uint32_t smem_to_u32(const void* smem_ptr) {
    uint32_t addr;
    asm("{ .reg .u64 tmp; cvta.to.shared.u64 tmp, %1; cvt.u32.u64 %0, tmp; }"
        : "=r"(addr) : "l"(smem_ptr));
    return addr;
}
#define LDMX4(r, addr) \
    asm volatile("ldmatrix.sync.aligned.m8n8.x4.shared.b16 {%0,%1,%2,%3}, [%4];" \
        : "=r"((r)[0]), "=r"((r)[1]), "=r"((r)[2]), "=r"((r)[3]) : "r"(addr))
#define MMA16816(d, a, b0, b1) \
    asm volatile("mma.sync.aligned.m16n8k16.row.col.f32.bf16.bf16.f32 " \
        "{%0,%1,%2,%3}, {%4,%5,%6,%7}, {%8,%9}, {%0,%1,%2,%3};" \
        : "+f"((d)[0]), "+f"((d)[1]), "+f"((d)[2]), "+f"((d)[3]) \
        : "r"((a)[0]), "r"((a)[1]), "r"((a)[2]), "r"((a)[3]), "r"(b0), "r"(b1))

__device__ __forceinline__ uint32_t pack_bf16(float lo_elem, float hi_elem) {
    __nv_bfloat162 p = __floats2bfloat162_rn(lo_elem, hi_elem);  // .x -> low 16 bits
    return *reinterpret_cast<uint32_t*>(&p);
}

// ---------------------------------------------------------------------------
// Prep: split W[128,128] (row-major [k][n]) into hi/lo bf16 transposed images
// Wt[n][k], pre-swizzled: byte(n,k) = n*256 + ((kc ^ (n&7))*16) + (k&7)*2
// ---------------------------------------------------------------------------
__global__ void prep_w_kernel(const float* __restrict__ W0,
                              const float* __restrict__ W1) {
    int idx = blockIdx.x * blockDim.x + threadIdx.x;   // 0 .. 16383
    if (idx >= 2 * 128 * 64) return;
    int layer = idx >> 13;
    int r = idx & 8191;
    int n = r >> 6;
    int kp = r & 63;
    int k = kp * 2;
    const float* W = layer ? W1 : W0;
    float w0 = W[(size_t)k * 128 + n];
    float w1 = W[(size_t)(k + 1) * 128 + n];
    __nv_bfloat16 h0 = __float2bfloat16_rn(w0);
    __nv_bfloat16 h1 = __float2bfloat16_rn(w1);
    uint32_t hp = pack_bf16(__bfloat162float(h0), __bfloat162float(h1));
    uint32_t lp = pack_bf16(w0 - __bfloat162float(h0), w1 - __bfloat162float(h1));
    int kc = k >> 3;
    uint32_t byte = (uint32_t)n * 256 + (uint32_t)((kc ^ (n & 7)) * 16) + (uint32_t)((k & 7) * 2);
    *reinterpret_cast<uint32_t*>(&g_Wimg[layer][0][byte]) = hp;
    *reinterpret_cast<uint32_t*>(&g_Wimg[layer][1][byte]) = lp;
}

// ---------------------------------------------------------------------------
// CSR build
// ---------------------------------------------------------------------------
__global__ void zero_cnt_kernel(int* __restrict__ cnt) {
    int i = blockIdx.x * blockDim.x + threadIdx.x;
    if (i < NN) cnt[i] = 0;
}
__global__ void hist_kernel(const int* __restrict__ ei, int* __restrict__ cnt) {
    int e = blockIdx.x * blockDim.x + threadIdx.x;
    if (e < NE) atomicAdd(&cnt[ei[NE + e]], 1);
}
__global__ void partial_sums_kernel(const int* __restrict__ cnt, int* __restrict__ part) {
    __shared__ int wsum[8];
    int i = blockIdx.x * SCAN_BLK + threadIdx.x;
    int v = (i < NN) ? cnt[i] : 0;
#pragma unroll
    for (int o = 16; o > 0; o >>= 1) v += __shfl_down_sync(0xffffffffu, v, o);
    int lane = threadIdx.x & 31, wid = threadIdx.x >> 5;
    if (lane == 0) wsum[wid] = v;
    __syncthreads();
    if (threadIdx.x == 0) {
        int s = 0;
#pragma unroll
        for (int w = 0; w < 8; w++) s += wsum[w];
        part[blockIdx.x] = s;
    }
}
__global__ void scan_partials_kernel(int* __restrict__ part) {
    __shared__ int s[512];
    int t = threadIdx.x;
    s[t] = (t < NBLK) ? part[t] : 0;
    __syncthreads();
    for (int o = 1; o < 512; o <<= 1) {
        int v = (t >= o) ? s[t - o] : 0;
        __syncthreads();
        s[t] += v;
        __syncthreads();
    }
    if (t < NBLK) part[t] = (t == 0) ? 0 : s[t - 1];
}
__global__ void make_offsets_kernel(const int* __restrict__ cnt,
                                    const int* __restrict__ part,
                                    int* __restrict__ start,
                                    int* __restrict__ cur) {
    __shared__ int wsum[8];
    int i = blockIdx.x * SCAN_BLK + threadIdx.x;
    int v = (i < NN) ? cnt[i] : 0;
    int lane = threadIdx.x & 31, wid = threadIdx.x >> 5;
    int x = v;
#pragma unroll
    for (int o = 1; o < 32; o <<= 1) {
        int y = __shfl_up_sync(0xffffffffu, x, o);
        if (lane >= o) x += y;
    }
    if (lane == 31) wsum[wid] = x;
    __syncthreads();
    if (wid == 0) {
        int w = (lane < 8) ? wsum[lane] : 0;
#pragma unroll
        for (int o = 1; o < 8; o <<= 1) {
            int y = __shfl_up_sync(0xffffffffu, w, o);
            if (lane >= o) w += y;
        }
        if (lane < 8) wsum[lane] = w;
    }
    __syncthreads();
    int ex = x - v + ((wid > 0) ? wsum[wid - 1] : 0) + part[blockIdx.x];
    if (i < NN) { start[i] = ex; cur[i] = ex; }
}
__global__ void fill_csr_kernel(const int* __restrict__ ei,
                                int* __restrict__ cur, int* __restrict__ csr) {
    int e = blockIdx.x * blockDim.x + threadIdx.x;
    if (e >= NE) return;
    int s = ei[e];
    int d = ei[NE + e];
    int p = atomicAdd(&cur[d], 1);
    csr[p] = s;
}

// ---------------------------------------------------------------------------
// Tensor-core GEMM via legacy mma.sync (bf16x3 split), 128-row tiles,
// double-buffered A staging (R10-proven configuration).
// SMEM: Wt_hi 32KB | Wt_lo 32KB | A dbuf 2 x (hi 4KB + lo 4KB) = 80 KB
// ---------------------------------------------------------------------------
#define SW_HI 0
#define SW_LO 32768
#define SA    65536
#define SM_TOTAL 81920

__global__ __launch_bounds__(256, 2) void gemm_mma_kernel(
    const float* __restrict__ in, const uint8_t* __restrict__ wimg_hi,
    const uint8_t* __restrict__ wimg_lo, float* __restrict__ out, int relu_in)
{
    extern __shared__ char smem[];
    const uint32_t sb = smem_to_u32(smem);
    const int tid = threadIdx.x;
    const int warp = tid >> 5;
    const int lane = tid & 31;
    const int row0 = blockIdx.x * 128;

    {
        const uint4* sh = (const uint4*)wimg_hi;
        const uint4* sl = (const uint4*)wimg_lo;
        uint4* dh = (uint4*)(smem + SW_HI);
        uint4* dl = (uint4*)(smem + SW_LO);
        for (int i = tid; i < 2048; i += 256) { dh[i] = sh[i]; dl[i] = sl[i]; }
    }

    float d[16][4];
#pragma unroll
    for (int t = 0; t < 16; t++)
#pragma unroll
        for (int j = 0; j < 4; j++) d[t][j] = 0.f;

    const int arow = tid >> 1;
    const int ahalf = tid & 1;
    const int gr_a = row0 + arow;
    const uint32_t a_st_byte = (uint32_t)arow * 32 + (uint32_t)((ahalf ^ ((arow >> 2) & 1)) << 4);

    const int lrow = (warp << 4) + (lane & 15);
    const int lh = lane >> 4;
    const uint32_t a_ld_off = (uint32_t)lrow * 32 + (uint32_t)((lh ^ ((lrow >> 2) & 1)) << 4);

    const int nLoc = ((lane >> 4) << 3) + (lane & 7);
    const int kcSel = (lane >> 3) & 1;

    auto stage = [&](int ks, int buf) {
        const int k0 = ks * 16;
        const uint32_t abase = (uint32_t)(SA + buf * 8192);
        float4 va = make_float4(0.f, 0.f, 0.f, 0.f), vb = va;
        if (gr_a < NN) {
            const float* src = in + (size_t)gr_a * D + k0 + ahalf * 8;
            va = *(const float4*)(src);
            vb = *(const float4*)(src + 4);
            if (relu_in) {
                va.x = fmaxf(va.x, 0.f); va.y = fmaxf(va.y, 0.f);
                va.z = fmaxf(va.z, 0.f); va.w = fmaxf(va.w, 0.f);
                vb.x = fmaxf(vb.x, 0.f); vb.y = fmaxf(vb.y, 0.f);
                vb.z = fmaxf(vb.z, 0.f); vb.w = fmaxf(vb.w, 0.f);
            }
        }
        float f[8] = {va.x, va.y, va.z, va.w, vb.x, vb.y, vb.z, vb.w};
        uint32_t hi[4], lo[4];
#pragma unroll
        for (int j = 0; j < 4; j++) {
            float x = f[2 * j], y = f[2 * j + 1];
            __nv_bfloat16 hx = __float2bfloat16_rn(x);
            __nv_bfloat16 hy = __float2bfloat16_rn(y);
            hi[j] = pack_bf16(__bfloat162float(hx), __bfloat162float(hy));
            lo[j] = pack_bf16(x - __bfloat162float(hx), y - __bfloat162float(hy));
        }
        *(uint4*)(smem + abase + a_st_byte) = make_uint4(hi[0], hi[1], hi[2], hi[3]);
        *(uint4*)(smem + abase + 4096 + a_st_byte) = make_uint4(lo[0], lo[1], lo[2], lo[3]);
    };

    stage(0, 0);
    __syncthreads();

    for (int ks = 0; ks < 8; ks++) {
        const int buf = ks & 1;
        const uint32_t abase = sb + SA + (uint32_t)buf * 8192;

        uint32_t ah[4], al[4];
        LDMX4(ah, abase + a_ld_off);
        LDMX4(al, abase + 4096 + a_ld_off);

        if (ks < 7) stage(ks + 1, buf ^ 1);

#pragma unroll
        for (int j = 0; j < 8; j++) {
            const int n = (j << 4) + nLoc;
            const int kc = (ks << 1) + kcSel;
            const uint32_t boff = (uint32_t)n * 256 + (uint32_t)((kc ^ (n & 7)) << 4);
            uint32_t bh[4], bl[4];
            LDMX4(bh, sb + SW_HI + boff);
            LDMX4(bl, sb + SW_LO + boff);
            MMA16816(d[2 * j],     ah, bh[0], bh[1]);
            MMA16816(d[2 * j],     ah, bl[0], bl[1]);
            MMA16816(d[2 * j],     al, bh[0], bh[1]);
            MMA16816(d[2 * j + 1], ah, bh[2], bh[3]);
            MMA16816(d[2 * j + 1], ah, bl[2], bl[3]);
            MMA16816(d[2 * j + 1], al, bh[2], bh[3]);
        }
        __syncthreads();
    }

    const int r0g = row0 + (warp << 4) + (lane >> 2);
    const int cbase = (lane & 3) * 2;
#pragma unroll
    for (int t = 0; t < 16; t++) {
        const int col = t * 8 + cbase;
        if (r0g < NN)
            *(float2*)(out + (size_t)r0g * D + col) = make_float2(d[t][0], d[t][1]);
        if (r0g + 8 < NN)
            *(float2*)(out + (size_t)(r0g + 8) * D + col) = make_float2(d[t][2], d[t][3]);
    }
}

// ---------------------------------------------------------------------------
// Gather: out[i] = bias + A[i] + sum_{j in nbrs(i)} A[j].   1 warp / node.
// ---------------------------------------------------------------------------
__global__ __launch_bounds__(256) void gather_kernel(
    const float* __restrict__ A, const int* __restrict__ start,
    const int* __restrict__ cnt, const int* __restrict__ csr,
    const float* __restrict__ bias, float* __restrict__ out)
{
    const int n = (blockIdx.x * blockDim.x + threadIdx.x) >> 5;
    if (n >= NN) return;
    const int lane = threadIdx.x & 31;
    const int c = lane * 4;

    float4 acc = *(const float4*)(A + (size_t)n * D + c);
    float4 b = *(const float4*)(bias + c);
    acc.x += b.x; acc.y += b.y; acc.z += b.z; acc.w += b.w;

    const int s0 = start[n];
    const int deg = cnt[n];

    for (int k0 = 0; k0 < deg; k0 += 32) {
        int idx = (k0 + lane < deg) ? csr[s0 + k0 + lane] : 0;
        int m = min(32, deg - k0);
        int j = 0;
        for (; j + 4 <= m; j += 4) {
            int n0 = __shfl_sync(0xffffffffu, idx, j);
            int n1 = __shfl_sync(0xffffffffu, idx, j + 1);
            int n2 = __shfl_sync(0xffffffffu, idx, j + 2);
            int n3 = __shfl_sync(0xffffffffu, idx, j + 3);
            float4 v0 = *(const float4*)(A + (size_t)n0 * D + c);
            float4 v1 = *(const float4*)(A + (size_t)n1 * D + c);
            float4 v2 = *(const float4*)(A + (size_t)n2 * D + c);
            float4 v3 = *(const float4*)(A + (size_t)n3 * D + c);
            acc.x += v0.x + v1.x + v2.x + v3.x;
            acc.y += v0.y + v1.y + v2.y + v3.y;
            acc.z += v0.z + v1.z + v2.z + v3.z;
            acc.w += v0.w + v1.w + v2.w + v3.w;
        }
        for (; j < m; j++) {
            int nb = __shfl_sync(0xffffffffu, idx, j);
            float4 v = *(const float4*)(A + (size_t)nb * D + c);
            acc.x += v.x; acc.y += v.y; acc.z += v.z; acc.w += v.w;
        }
    }
    *(float4*)(out + (size_t)n * D + c) = acc;
}

// ---------------------------------------------------------------------------
// Readout
// ---------------------------------------------------------------------------
__global__ __launch_bounds__(128) void readout_kernel(
    const float* __restrict__ h, const float* __restrict__ Wf,
    const float* __restrict__ bf, const int* __restrict__ gsz,
    float* __restrict__ out)
{
    __shared__ float Wfs[D][NT];
    __shared__ float bfs[NT];
    __shared__ float sums[NT];

    const int tid = threadIdx.x;
    const int g = blockIdx.x;

    for (int i = tid; i < D * NT; i += 128) Wfs[i / NT][i % NT] = Wf[i];
    if (tid < NT) { bfs[tid] = bf[tid]; sums[tid] = 0.f; }
    __syncthreads();

    const int sz = gsz[g];
    if (tid < sz) {
        const float* row = h + ((size_t)g * 100 + tid) * D;
        float a[NT];
#pragma unroll
        for (int t = 0; t < NT; t++) a[t] = bfs[t];
        for (int k0 = 0; k0 < D; k0 += 4) {
            float4 hv = *(const float4*)(row + k0);
            hv.x = fmaxf(hv.x, 0.f); hv.y = fmaxf(hv.y, 0.f);
            hv.z = fmaxf(hv.z, 0.f); hv.w = fmaxf(hv.w, 0.f);
#pragma unroll
            for (int t = 0; t < NT; t++) {
                a[t] = fmaf(hv.x, Wfs[k0 + 0][t], a[t]);
                a[t] = fmaf(hv.y, Wfs[k0 + 1][t], a[t]);
                a[t] = fmaf(hv.z, Wfs[k0 + 2][t], a[t]);
                a[t] = fmaf(hv.w, Wfs[k0 + 3][t], a[t]);
            }
        }
#pragma unroll
        for (int t = 0; t < NT; t++) {
            float s = 1.f / (1.f + expf(-a[t]));
            atomicAdd(&sums[t], s);
        }
    }
    __syncthreads();
    if (tid < NT) out[(size_t)g * NT + tid] = sums[tid] / (float)sz;
}

// ---------------------------------------------------------------------------
extern "C" void kernel_launch(void* const* d_in, const int* in_sizes, int n_in,
                              void* d_out, int out_size)
{
    const float* X   = (const float*)d_in[0];
    const int*   ei  = (const int*)d_in[1];
    const int*   gsz = (const int*)d_in[2];
    const float* W0  = (const float*)d_in[3];
    const float* b0  = (const float*)d_in[4];
    const float* W1  = (const float*)d_in[5];
    const float* b1  = (const float*)d_in[6];
    const float* Wf  = (const float*)d_in[7];
    const float* bf  = (const float*)d_in[8];
    float* out = (float*)d_out;

    float *A, *B, *C;
    int *cnt, *start, *cur, *part, *csr;
    uint8_t* wimg;
    cudaGetSymbolAddress((void**)&A, g_A);
    cudaGetSymbolAddress((void**)&B, g_B);
    cudaGetSymbolAddress((void**)&C, g_C);
    cudaGetSymbolAddress((void**)&cnt, g_cnt);
    cudaGetSymbolAddress((void**)&start, g_start);
    cudaGetSymbolAddress((void**)&cur, g_cur);
    cudaGetSymbolAddress((void**)&part, g_part);
    cudaGetSymbolAddress((void**)&csr, g_csr);
    cudaGetSymbolAddress((void**)&wimg, g_Wimg);

    cudaFuncSetAttribute(gemm_mma_kernel,
                         cudaFuncAttributeMaxDynamicSharedMemorySize, SM_TOTAL);

    const int edge_blocks = (NE + 255) / 256;
    const int node_warp_blocks = (NN * 32 + 255) / 256;

    cudaStream_t s2 = g_fork.s2;

    // ---- fork: CSR build chain on HIGH-PRIORITY side stream ----
    cudaEventRecord(g_fork.evFork, 0);
    cudaStreamWaitEvent(s2, g_fork.evFork, 0);

    zero_cnt_kernel<<<NBLK, SCAN_BLK, 0, s2>>>(cnt);
    hist_kernel<<<edge_blocks, 256, 0, s2>>>(ei, cnt);
    partial_sums_kernel<<<NBLK, SCAN_BLK, 0, s2>>>(cnt, part);
    scan_partials_kernel<<<1, 512, 0, s2>>>(part);
    make_offsets_kernel<<<NBLK, SCAN_BLK, 0, s2>>>(cnt, part, start, cur);
    fill_csr_kernel<<<edge_blocks, 256, 0, s2>>>(ei, cur, csr);
    cudaEventRecord(g_fork.evJoin, s2);

    // ---- main stream: weight prep + GEMM1 (concurrent with CSR) ----
    const uint8_t* w0h = wimg;
    const uint8_t* w0l = wimg + 32768;
    const uint8_t* w1h = wimg + 65536;
    const uint8_t* w1l = wimg + 98304;

    prep_w_kernel<<<64, 256>>>(W0, W1);
    gemm_mma_kernel<<<MTILES, 256, SM_TOTAL>>>(X, w0h, w0l, A, 0);

    // ---- join: gather needs both GEMM1 (A) and the CSR arrays ----
    cudaStreamWaitEvent(0, g_fork.evJoin, 0);

    // Layer 1: B = b0 + A + gather(A)
    gather_kernel<<<node_warp_blocks, 256>>>(A, start, cnt, csr, b0, B);

    // Layer 2: A = relu(B)@W1 ; C = b1 + A + gather(A)
    gemm_mma_kernel<<<MTILES, 256, SM_TOTAL>>>(B, w1h, w1l, A, 1);
    gather_kernel<<<node_warp_blocks, 256>>>(A, start, cnt, csr, b1, C);

    // Head
    readout_kernel<<<NG, 128>>>(C, Wf, bf, gsz, out);
}